// round 14
// baseline (speedup 1.0000x reference)
#include <cuda_runtime.h>
#include <cuda_bf16.h>
#include <math_constants.h>
#include <cstdint>

// ---------------------------------------------------------------------------
// DGCNN forward, B=8 C=3 N=2048 k=20, emb dims 64/64/128/256/512.
// kNN exact fp32 (reference evaluation order). Conv GEMMs via warp-level
// mma.sync bf16 (m16n8k16) with bf16x3 decomposition (h*h + h*l + l*h),
// fp32 accumulators: rel err ~2^-16. BN folded on load, stats fused into
// the GEMM epilogue. (tcgen05 unavailable: harness targets compute_103.)
// R12 fix: __syncthreads() between BN-table fill and first chunk load.
// ---------------------------------------------------------------------------

#define BATCH 8
#define NPTS  2048
#define KNN   20
#define Q     (BATCH * NPTS)        // 16384
#define P1    (Q * KNN)             // 327680

__device__ int    g_idx[P1];
__device__ float  g_y1[(size_t)64  * P1];
__device__ float  g_y2[(size_t)64  * P1];
__device__ float  g_y3[(size_t)128 * P1];
__device__ float  g_y4[(size_t)256 * P1];
__device__ float  g_xcat[(size_t)512 * Q];
__device__ float  g_y5[(size_t)512 * Q];
__device__ double g_sum[1024];
__device__ double g_sumsq[1024];
__device__ float  g_scale[1024];
__device__ float  g_shift[1024];

__device__ __forceinline__ uint32_t smem_u32(const void* p) {
    uint32_t r;
    asm("{ .reg .u64 t; cvta.to.shared.u64 t, %1; cvt.u32.u64 %0, t; }"
        : "=r"(r) : "l"(p));
    return r;
}

#define LDSM_X4(r0, r1, r2, r3, addr) \
    asm volatile("ldmatrix.sync.aligned.m8n8.x4.shared.b16 {%0,%1,%2,%3}, [%4];" \
        : "=r"(r0), "=r"(r1), "=r"(r2), "=r"(r3) : "r"(addr))

#define MMA_BF16(c, a, b0v, b1v) \
    asm volatile("mma.sync.aligned.m16n8k16.row.col.f32.bf16.bf16.f32 " \
        "{%0,%1,%2,%3}, {%4,%5,%6,%7}, {%8,%9}, {%0,%1,%2,%3};" \
        : "+f"((c)[0]), "+f"((c)[1]), "+f"((c)[2]), "+f"((c)[3]) \
        : "r"((a)[0]), "r"((a)[1]), "r"((a)[2]), "r"((a)[3]), \
          "r"(b0v), "r"(b1v))

__device__ __forceinline__ uint32_t pack_hi(float a, float b, uint32_t& lo) {
    __nv_bfloat16 ha = __float2bfloat16(a);
    __nv_bfloat16 hb = __float2bfloat16(b);
    __nv_bfloat16 la = __float2bfloat16(a - __bfloat162float(ha));
    __nv_bfloat16 lb = __float2bfloat16(b - __bfloat162float(hb));
    lo = (uint32_t)__bfloat16_as_ushort(la) | ((uint32_t)__bfloat16_as_ushort(lb) << 16);
    return (uint32_t)__bfloat16_as_ushort(ha) | ((uint32_t)__bfloat16_as_ushort(hb) << 16);
}

// ---------------------------------------------------------------------------
// kNN: one warp per query (exact fp32 reference evaluation order).
// ---------------------------------------------------------------------------
__global__ void knn_kernel(const float* __restrict__ x, int* __restrict__ idx_out) {
    __shared__ float sd[4][NPTS];
    const int warp = threadIdx.x >> 5;
    const int lane = threadIdx.x & 31;
    const int query = blockIdx.x * 4 + warp;
    const int b = query >> 11;
    const int i = query & (NPTS - 1);
    const float* xb = x + (size_t)b * 3 * NPTS;

    const float xi0 = xb[i], xi1 = xb[NPTS + i], xi2 = xb[2 * NPTS + i];
    const float xxi = __fadd_rn(__fadd_rn(__fmul_rn(xi0, xi0), __fmul_rn(xi1, xi1)),
                                __fmul_rn(xi2, xi2));

    float* d = sd[warp];
    for (int j = lane; j < NPTS; j += 32) {
        float a0 = xb[j], a1 = xb[NPTS + j], a2 = xb[2 * NPTS + j];
        float xxj = __fadd_rn(__fadd_rn(__fmul_rn(a0, a0), __fmul_rn(a1, a1)),
                              __fmul_rn(a2, a2));
        float dot = fmaf(xi2, a2, fmaf(xi1, a1, __fmul_rn(xi0, a0)));
        d[j] = __fsub_rn(__fsub_rn(2.0f * dot, xxi), xxj);
    }
    __syncwarp();

    int* out = idx_out + query * KNN;
    for (int t = 0; t < KNN; t++) {
        float best = -CUDART_INF_F;
        int bi = NPTS;
        for (int j = lane; j < NPTS; j += 32) {
            float v = d[j];
            if (v > best) { best = v; bi = j; }
        }
        #pragma unroll
        for (int off = 16; off; off >>= 1) {
            float ov = __shfl_xor_sync(0xffffffffu, best, off);
            int   oi = __shfl_xor_sync(0xffffffffu, bi, off);
            if (ov > best || (ov == best && oi < bi)) { best = ov; bi = oi; }
        }
        if (lane == 0) { out[t] = bi; d[bi] = -CUDART_INF_F; }
        __syncwarp();
    }
}

// ---------------------------------------------------------------------------
// Layer 1: gather edge feature (Cin=6) + 64x6 matvec, raw y out.
// ---------------------------------------------------------------------------
__global__ void layer1_kernel(const float* __restrict__ x, const int* __restrict__ idx,
                              const float* __restrict__ w1, float* __restrict__ y1) {
    __shared__ float ws[64 * 6];
    const int tid = threadIdx.x;
    for (int t = tid; t < 64 * 6; t += 256) ws[t] = w1[t];
    __syncthreads();

    const int p = blockIdx.x * 256 + tid;
    const int q = p / KNN;
    const int b = q >> 11;
    const int n = q & (NPTS - 1);
    const int j = idx[p];
    const float* xb = x + (size_t)b * 3 * NPTS;

    const float xi0 = xb[n], xi1 = xb[NPTS + n], xi2 = xb[2 * NPTS + n];
    const float f0 = xb[j] - xi0;
    const float f1 = xb[NPTS + j] - xi1;
    const float f2 = xb[2 * NPTS + j] - xi2;
    const float f3 = xi0, f4 = xi1, f5 = xi2;

    #pragma unroll 8
    for (int o = 0; o < 64; o++) {
        const float* w = ws + o * 6;
        float acc = fmaf(w[5], f5, fmaf(w[4], f4, fmaf(w[3], f3,
                    fmaf(w[2], f2, fmaf(w[1], f1, w[0] * f0)))));
        y1[(size_t)o * P1 + p] = acc;
    }
}

// ---------------------------------------------------------------------------
// bf16x3 MMA GEMM: Y[O,P] = W[O,Cin] * act(X[Cin,P]).
// CTA: 128p x 64o, k-chunks of 16, double-buffered smem with hi/lo planes.
// 8 warps = 4(p) x 2(o); warp tile 32p x 32o = 2 x 4 m16n8k16 atoms.
// smem rows padded to 48B (conflict-free ldmatrix). Epilogue stages D
// through smem for coalesced stores + fused per-channel sum/sumsq.
// Requires P%128==0, O%64==0, Cin%16==0.
// ---------------------------------------------------------------------------
#define AHI_OFF 0
#define ALO_OFF 6144
#define BHI_OFF 12288
#define BLO_OFF 15360
#define BUF_SZ  18432

__global__ __launch_bounds__(256)
void gemm_mma(const float* __restrict__ W, const float* __restrict__ X,
              float* __restrict__ Y, int Cin, int P,
              const float* __restrict__ scale, const float* __restrict__ shift,
              double* __restrict__ sumO, double* __restrict__ sqO) {
    __shared__ __align__(128) char sbuf[2][BUF_SZ];
    __shared__ float ssc[512], ssh[512];
    __shared__ float s_sum[64], s_sq[64];

    const int tid = threadIdx.x, wid = tid >> 5, lane = tid & 31;
    const int p0 = blockIdx.x * 128;
    const int o0 = blockIdx.y * 64;
    const bool bn = (scale != nullptr);

    if (bn) for (int c = tid; c < Cin; c += 256) { ssc[c] = scale[c]; ssh[c] = shift[c]; }
    if (tid < 64) { s_sum[tid] = 0.f; s_sq[tid] = 0.f; }
    __syncthreads();   // R12 FIX: ssc/ssh (and s_sum) visible before first use

    const int m0 = (wid & 3) * 32;     // warp p-base within tile
    const int n0 = (wid >> 2) * 32;    // warp o-base within tile
    const int g = lane >> 2, tq = lane & 3;

    // global-load mapping (per chunk of 16 k):
    //   A: thread -> k-pair kp = tid>>5 (0..7), p-float4 p4 = tid&31
    //   B: thread -> o = tid>>2 (0..63), k-float4 k4 = tid&3
    const int kp = tid >> 5, p4 = tid & 31;
    const int bo = tid >> 2, k4 = tid & 3;

    float acc[2][4][4];
    #pragma unroll
    for (int i = 0; i < 2; i++)
        #pragma unroll
        for (int j = 0; j < 4; j++)
            #pragma unroll
            for (int r = 0; r < 4; r++) acc[i][j][r] = 0.f;

    const int KT = Cin >> 4;
    float4 va0, va1, vb;

    // ---- staged load of chunk c into registers ----
    auto load_chunk = [&](int ci) {
        const int c0 = ci * 16;
        const float* xp = X + (size_t)(c0 + 2 * kp) * P + p0 + 4 * p4;
        va0 = *reinterpret_cast<const float4*>(xp);
        va1 = *reinterpret_cast<const float4*>(xp + P);
        if (bn) {
            float s0 = ssc[c0 + 2 * kp], h0 = ssh[c0 + 2 * kp];
            float s1 = ssc[c0 + 2 * kp + 1], h1 = ssh[c0 + 2 * kp + 1];
            va0.x = fmaxf(fmaf(va0.x, s0, h0), 0.f);
            va0.y = fmaxf(fmaf(va0.y, s0, h0), 0.f);
            va0.z = fmaxf(fmaf(va0.z, s0, h0), 0.f);
            va0.w = fmaxf(fmaf(va0.w, s0, h0), 0.f);
            va1.x = fmaxf(fmaf(va1.x, s1, h1), 0.f);
            va1.y = fmaxf(fmaf(va1.y, s1, h1), 0.f);
            va1.z = fmaxf(fmaf(va1.z, s1, h1), 0.f);
            va1.w = fmaxf(fmaf(va1.w, s1, h1), 0.f);
        }
        vb = *reinterpret_cast<const float4*>(W + (size_t)(o0 + bo) * Cin + c0 + 4 * k4);
    };

    auto store_chunk = [&](int buf) {
        char* bb = sbuf[buf];
        // A: rows 4*p4..+3, k-pair kp -> byte row*48 + kp*4
        const float a0v[4] = {va0.x, va0.y, va0.z, va0.w};
        const float a1v[4] = {va1.x, va1.y, va1.z, va1.w};
        #pragma unroll
        for (int j = 0; j < 4; j++) {
            uint32_t lo;
            uint32_t hi = pack_hi(a0v[j], a1v[j], lo);   // low half = even k
            uint32_t off = (uint32_t)(4 * p4 + j) * 48 + kp * 4;
            *reinterpret_cast<uint32_t*>(bb + AHI_OFF + off) = hi;
            *reinterpret_cast<uint32_t*>(bb + ALO_OFF + off) = lo;
        }
        // B: row o, k-pairs 2*k4, 2*k4+1 -> byte o*48 + k4*8
        uint32_t lo01, lo23;
        uint32_t hi01 = pack_hi(vb.x, vb.y, lo01);
        uint32_t hi23 = pack_hi(vb.z, vb.w, lo23);
        uint32_t boff = (uint32_t)bo * 48 + k4 * 8;
        *reinterpret_cast<uint2*>(bb + BHI_OFF + boff) = make_uint2(hi01, hi23);
        *reinterpret_cast<uint2*>(bb + BLO_OFF + boff) = make_uint2(lo01, lo23);
    };

    load_chunk(0);
    store_chunk(0);
    __syncthreads();

    for (int kt = 0; kt < KT; kt++) {
        const int buf = kt & 1;
        if (kt + 1 < KT) load_chunk(kt + 1);

        const uint32_t base = smem_u32(sbuf[buf]);
        // A fragments (hi & lo) for both m-atoms
        uint32_t ah[2][4], al[2][4];
        #pragma unroll
        for (int ma = 0; ma < 2; ma++) {
            uint32_t roff = (uint32_t)(m0 + ma * 16 + (lane & 15)) * 48
                          + ((lane >> 4) & 1) * 16;
            LDSM_X4(ah[ma][0], ah[ma][1], ah[ma][2], ah[ma][3], base + AHI_OFF + roff);
            LDSM_X4(al[ma][0], al[ma][1], al[ma][2], al[ma][3], base + ALO_OFF + roff);
        }
        // B fragments: x4 packs n-atom pair (2jp, 2jp+1)
        uint32_t bh[4][2], bl[4][2];
        #pragma unroll
        for (int jp = 0; jp < 2; jp++) {
            uint32_t roff = (uint32_t)(n0 + jp * 16 + (lane & 7) + ((lane >> 4) & 1) * 8) * 48
                          + ((lane >> 3) & 1) * 16;
            LDSM_X4(bh[2 * jp][0], bh[2 * jp][1], bh[2 * jp + 1][0], bh[2 * jp + 1][1],
                    base + BHI_OFF + roff);
            LDSM_X4(bl[2 * jp][0], bl[2 * jp][1], bl[2 * jp + 1][0], bl[2 * jp + 1][1],
                    base + BLO_OFF + roff);
        }

        #pragma unroll
        for (int ma = 0; ma < 2; ma++)
            #pragma unroll
            for (int na = 0; na < 4; na++) {
                MMA_BF16(acc[ma][na], ah[ma], bh[na][0], bh[na][1]);
                MMA_BF16(acc[ma][na], ah[ma], bl[na][0], bl[na][1]);
                MMA_BF16(acc[ma][na], al[ma], bh[na][0], bh[na][1]);
            }
        __syncthreads();

        if (kt + 1 < KT) {
            store_chunk(buf ^ 1);
            __syncthreads();
        }
    }

    // ---- epilogue: stage D via smem, coalesced store + fused stats ----
    float (*yt)[132] = reinterpret_cast<float(*)[132]>(sbuf[0]);
    #pragma unroll
    for (int ma = 0; ma < 2; ma++) {
        const int p = m0 + ma * 16 + g;
        #pragma unroll
        for (int na = 0; na < 4; na++) {
            const int o = n0 + na * 8 + tq * 2;
            yt[o][p]         = acc[ma][na][0];
            yt[o + 1][p]     = acc[ma][na][1];
            yt[o][p + 8]     = acc[ma][na][2];
            yt[o + 1][p + 8] = acc[ma][na][3];
        }
    }
    __syncthreads();

    {   // stats: thread -> row o = tid>>2, segment (tid&3)*32
        const int o = tid >> 2, seg = (tid & 3) * 32;
        float s = 0.f, q2 = 0.f;
        #pragma unroll
        for (int i = 0; i < 32; i++) {
            float v = yt[o][seg + i];
            s += v;
            q2 = fmaf(v, v, q2);
        }
        atomicAdd(&s_sum[o], s);
        atomicAdd(&s_sq[o], q2);
    }

    #pragma unroll
    for (int i = 0; i < 8; i++) {
        const int lin = i * 256 + tid;
        const int o = lin >> 5, pp = (lin & 31) * 4;
        *reinterpret_cast<float4*>(&Y[(size_t)(o0 + o) * P + p0 + pp]) =
            *reinterpret_cast<const float4*>(&yt[o][pp]);
    }
    __syncthreads();
    if (tid < 64) {
        atomicAdd(&sumO[o0 + tid], (double)s_sum[tid]);
        atomicAdd(&sqO[o0 + tid], (double)s_sq[tid]);
    }
}

// ---------------------------------------------------------------------------
// Per-channel sum / sumsq (double) over raw y (layer 1 only).
// ---------------------------------------------------------------------------
__global__ void stats_kernel(const float* __restrict__ Yv, double* __restrict__ sum,
                             double* __restrict__ sumsq, int P) {
    const int c = blockIdx.y;
    const float* row = Yv + (size_t)c * P;
    const int base = blockIdx.x * 4096 + threadIdx.x;
    double s = 0.0, ss = 0.0;
    #pragma unroll
    for (int u = 0; u < 16; u++) {
        int p = base + u * 256;
        if (p < P) { double v = (double)row[p]; s += v; ss += v * v; }
    }
    #pragma unroll
    for (int off = 16; off; off >>= 1) {
        s  += __shfl_down_sync(0xffffffffu, s,  off);
        ss += __shfl_down_sync(0xffffffffu, ss, off);
    }
    __shared__ double sw[8], ssw[8];
    const int lane = threadIdx.x & 31, w = threadIdx.x >> 5;
    if (lane == 0) { sw[w] = s; ssw[w] = ss; }
    __syncthreads();
    if (threadIdx.x == 0) {
        double S = 0.0, SS = 0.0;
        #pragma unroll
        for (int i = 0; i < 8; i++) { S += sw[i]; SS += ssw[i]; }
        atomicAdd(&sum[c], S);
        atomicAdd(&sumsq[c], SS);
    }
}

__global__ void finalize_kernel(const float* __restrict__ g, const float* __restrict__ bb,
                                const double* __restrict__ sum, const double* __restrict__ sumsq,
                                float* __restrict__ scale, float* __restrict__ shift,
                                int C, double invcnt) {
    int c = threadIdx.x;
    if (c >= C) return;
    double m = sum[c] * invcnt;
    double v = sumsq[c] * invcnt - m * m;
    if (v < 0.0) v = 0.0;
    float rstd = rsqrtf((float)v + 1e-5f);
    float sc = g[c] * rstd;
    scale[c] = sc;
    shift[c] = bb[c] - (float)m * sc;
}

// ---------------------------------------------------------------------------
// BN + ReLU + max over k=20; writes into concat buffer at channel offset.
// ---------------------------------------------------------------------------
__global__ void max_kernel(const float* __restrict__ Yv, const float* __restrict__ scale,
                           const float* __restrict__ shift, float* __restrict__ outp, int C) {
    const int t = blockIdx.x * 256 + threadIdx.x;
    const int c = t >> 14;
    const int q = t & 16383;
    const float* src = Yv + (size_t)c * P1 + (size_t)q * KNN;
    const float sc = scale[c], sh = shift[c];
    float m = 0.f;
    #pragma unroll
    for (int k = 0; k < KNN; k++) m = fmaxf(m, fmaf(src[k], sc, sh));
    outp[(size_t)c * Q + q] = m;
}

__global__ void final_kernel(const float* __restrict__ y5, const float* __restrict__ scale,
                             const float* __restrict__ shift, float* __restrict__ out) {
    const int t = blockIdx.x * 256 + threadIdx.x;
    const int n = t & (NPTS - 1);
    const int c = (t >> 11) & 511;
    const int b = t >> 20;
    float v = y5[(size_t)c * Q + b * NPTS + n];
    out[t] = fmaxf(fmaf(v, scale[c], shift[c]), 0.f);
}

// ---------------------------------------------------------------------------
extern "C" void kernel_launch(void* const* d_in, const int* in_sizes, int n_in,
                              void* d_out, int out_size) {
    const float* x  = (const float*)d_in[0];
    const float* w1 = (const float*)d_in[1];
    const float* g1 = (const float*)d_in[2];
    const float* b1 = (const float*)d_in[3];
    const float* w2 = (const float*)d_in[4];
    const float* g2 = (const float*)d_in[5];
    const float* b2 = (const float*)d_in[6];
    const float* w3 = (const float*)d_in[7];
    const float* g3 = (const float*)d_in[8];
    const float* b3 = (const float*)d_in[9];
    const float* w4 = (const float*)d_in[10];
    const float* g4 = (const float*)d_in[11];
    const float* b4 = (const float*)d_in[12];
    const float* w5 = (const float*)d_in[13];
    const float* g5 = (const float*)d_in[14];
    const float* b5 = (const float*)d_in[15];
    float* out = (float*)d_out;

    int *idxp; float *y1, *y2, *y3, *y4, *xcat, *y5, *scal, *shif;
    double *sum, *sumsq;
    cudaGetSymbolAddress((void**)&idxp,  g_idx);
    cudaGetSymbolAddress((void**)&y1,    g_y1);
    cudaGetSymbolAddress((void**)&y2,    g_y2);
    cudaGetSymbolAddress((void**)&y3,    g_y3);
    cudaGetSymbolAddress((void**)&y4,    g_y4);
    cudaGetSymbolAddress((void**)&xcat,  g_xcat);
    cudaGetSymbolAddress((void**)&y5,    g_y5);
    cudaGetSymbolAddress((void**)&sum,   g_sum);
    cudaGetSymbolAddress((void**)&sumsq, g_sumsq);
    cudaGetSymbolAddress((void**)&scal,  g_scale);
    cudaGetSymbolAddress((void**)&shif,  g_shift);

    const double ic1 = 1.0 / (double)P1;
    const double ic5 = 1.0 / (double)Q;

    cudaMemsetAsync(sum,   0, 1024 * sizeof(double));
    cudaMemsetAsync(sumsq, 0, 1024 * sizeof(double));

    knn_kernel<<<Q / 4, 128>>>(x, idxp);
    layer1_kernel<<<P1 / 256, 256>>>(x, idxp, w1, y1);

    stats_kernel<<<dim3(80, 64), 256>>>(y1, sum + 0, sumsq + 0, P1);
    finalize_kernel<<<1, 64>>>(g1, b1, sum + 0, sumsq + 0, scal + 0, shif + 0, 64, ic1);
    max_kernel<<<64 * Q / 256, 256>>>(y1, scal + 0, shif + 0, xcat, 64);

    gemm_mma<<<dim3(P1 / 128, 1), 256>>>(w2, y1, y2, 64, P1,
                                         scal + 0, shif + 0, sum + 64, sumsq + 64);
    finalize_kernel<<<1, 64>>>(g2, b2, sum + 64, sumsq + 64, scal + 64, shif + 64, 64, ic1);
    max_kernel<<<64 * Q / 256, 256>>>(y2, scal + 64, shif + 64, xcat + (size_t)64 * Q, 64);

    gemm_mma<<<dim3(P1 / 128, 2), 256>>>(w3, y2, y3, 64, P1,
                                         scal + 64, shif + 64, sum + 128, sumsq + 128);
    finalize_kernel<<<1, 128>>>(g3, b3, sum + 128, sumsq + 128, scal + 128, shif + 128, 128, ic1);
    max_kernel<<<128 * Q / 256, 256>>>(y3, scal + 128, shif + 128, xcat + (size_t)128 * Q, 128);

    gemm_mma<<<dim3(P1 / 128, 4), 256>>>(w4, y3, y4, 128, P1,
                                         scal + 128, shif + 128, sum + 256, sumsq + 256);
    finalize_kernel<<<1, 256>>>(g4, b4, sum + 256, sumsq + 256, scal + 256, shif + 256, 256, ic1);
    max_kernel<<<256 * Q / 256, 256>>>(y4, scal + 256, shif + 256, xcat + (size_t)256 * Q, 256);

    gemm_mma<<<dim3(Q / 128, 8), 256>>>(w5, xcat, y5, 512, Q,
                                        nullptr, nullptr, sum + 512, sumsq + 512);
    finalize_kernel<<<1, 512>>>(g5, b5, sum + 512, sumsq + 512, scal + 512, shif + 512, 512, ic5);
    final_kernel<<<(BATCH * 512 * NPTS) / 256, 256>>>(y5, scal + 512, shif + 512, out);
}

// round 15
// speedup vs baseline: 1.0687x; 1.0687x over previous
#include <cuda_runtime.h>
#include <cuda_bf16.h>
#include <math_constants.h>
#include <cstdint>

// ---------------------------------------------------------------------------
// DGCNN forward, B=8 C=3 N=2048 k=20, emb dims 64/64/128/256/512.
// kNN exact fp32 (reference evaluation order). Conv GEMMs via warp-level
// mma.sync bf16 (m16n8k16), bf16x3 decomposition (h*h + h*l + l*h), fp32
// accumulators (rel err ~2^-16). R15: k-chunk 32, o-tile 128 for L3-L5,
// pre-packed bf16 weight planes, stats fused in epilogue.
// ---------------------------------------------------------------------------

#define BATCH 8
#define NPTS  2048
#define KNN   20
#define Q     (BATCH * NPTS)        // 16384
#define P1    (Q * KNN)             // 327680

__device__ int    g_idx[P1];
__device__ float  g_y1[(size_t)64  * P1];
__device__ float  g_y2[(size_t)64  * P1];
__device__ float  g_y3[(size_t)128 * P1];
__device__ float  g_y4[(size_t)256 * P1];
__device__ float  g_xcat[(size_t)512 * Q];
__device__ float  g_y5[(size_t)512 * Q];
__device__ double g_sum[1024];
__device__ double g_sumsq[1024];
__device__ float  g_scale[1024];
__device__ float  g_shift[1024];
__device__ __nv_bfloat16 g_whi[307200];   // packed W hi planes (all layers)
__device__ __nv_bfloat16 g_wlo[307200];   // packed W lo planes

__device__ __forceinline__ uint32_t smem_u32(const void* p) {
    uint32_t r;
    asm("{ .reg .u64 t; cvta.to.shared.u64 t, %1; cvt.u32.u64 %0, t; }"
        : "=r"(r) : "l"(p));
    return r;
}

#define LDSM_X4(r0, r1, r2, r3, addr) \
    asm volatile("ldmatrix.sync.aligned.m8n8.x4.shared.b16 {%0,%1,%2,%3}, [%4];" \
        : "=r"(r0), "=r"(r1), "=r"(r2), "=r"(r3) : "r"(addr))

#define MMA_BF16(c, a, b0v, b1v) \
    asm volatile("mma.sync.aligned.m16n8k16.row.col.f32.bf16.bf16.f32 " \
        "{%0,%1,%2,%3}, {%4,%5,%6,%7}, {%8,%9}, {%0,%1,%2,%3};" \
        : "+f"((c)[0]), "+f"((c)[1]), "+f"((c)[2]), "+f"((c)[3]) \
        : "r"((a)[0]), "r"((a)[1]), "r"((a)[2]), "r"((a)[3]), \
          "r"(b0v), "r"(b1v))

__device__ __forceinline__ uint32_t pack_hi(float a, float b, uint32_t& lo) {
    __nv_bfloat16 ha = __float2bfloat16(a);
    __nv_bfloat16 hb = __float2bfloat16(b);
    __nv_bfloat16 la = __float2bfloat16(a - __bfloat162float(ha));
    __nv_bfloat16 lb = __float2bfloat16(b - __bfloat162float(hb));
    lo = (uint32_t)__bfloat16_as_ushort(la) | ((uint32_t)__bfloat16_as_ushort(lb) << 16);
    return (uint32_t)__bfloat16_as_ushort(ha) | ((uint32_t)__bfloat16_as_ushort(hb) << 16);
}

// ---------------------------------------------------------------------------
__global__ void pack_w(const float* __restrict__ w, __nv_bfloat16* __restrict__ hi,
                       __nv_bfloat16* __restrict__ lo, int n) {
    int i = blockIdx.x * 256 + threadIdx.x;
    if (i >= n) return;
    float f = w[i];
    __nv_bfloat16 h = __float2bfloat16(f);
    hi[i] = h;
    lo[i] = __float2bfloat16(f - __bfloat162float(h));
}

// ---------------------------------------------------------------------------
// kNN: one warp per query (exact fp32 reference evaluation order).
// ---------------------------------------------------------------------------
__global__ void knn_kernel(const float* __restrict__ x, int* __restrict__ idx_out) {
    __shared__ float sd[4][NPTS];
    const int warp = threadIdx.x >> 5;
    const int lane = threadIdx.x & 31;
    const int query = blockIdx.x * 4 + warp;
    const int b = query >> 11;
    const int i = query & (NPTS - 1);
    const float* xb = x + (size_t)b * 3 * NPTS;

    const float xi0 = xb[i], xi1 = xb[NPTS + i], xi2 = xb[2 * NPTS + i];
    const float xxi = __fadd_rn(__fadd_rn(__fmul_rn(xi0, xi0), __fmul_rn(xi1, xi1)),
                                __fmul_rn(xi2, xi2));

    float* d = sd[warp];
    for (int j = lane; j < NPTS; j += 32) {
        float a0 = xb[j], a1 = xb[NPTS + j], a2 = xb[2 * NPTS + j];
        float xxj = __fadd_rn(__fadd_rn(__fmul_rn(a0, a0), __fmul_rn(a1, a1)),
                              __fmul_rn(a2, a2));
        float dot = fmaf(xi2, a2, fmaf(xi1, a1, __fmul_rn(xi0, a0)));
        d[j] = __fsub_rn(__fsub_rn(2.0f * dot, xxi), xxj);
    }
    __syncwarp();

    int* out = idx_out + query * KNN;
    for (int t = 0; t < KNN; t++) {
        float best = -CUDART_INF_F;
        int bi = NPTS;
        for (int j = lane; j < NPTS; j += 32) {
            float v = d[j];
            if (v > best) { best = v; bi = j; }
        }
        #pragma unroll
        for (int off = 16; off; off >>= 1) {
            float ov = __shfl_xor_sync(0xffffffffu, best, off);
            int   oi = __shfl_xor_sync(0xffffffffu, bi, off);
            if (ov > best || (ov == best && oi < bi)) { best = ov; bi = oi; }
        }
        if (lane == 0) { out[t] = bi; d[bi] = -CUDART_INF_F; }
        __syncwarp();
    }
}

// ---------------------------------------------------------------------------
// Layer 1: gather edge feature (Cin=6) + 64x6 matvec, raw y out.
// ---------------------------------------------------------------------------
__global__ void layer1_kernel(const float* __restrict__ x, const int* __restrict__ idx,
                              const float* __restrict__ w1, float* __restrict__ y1) {
    __shared__ float ws[64 * 6];
    const int tid = threadIdx.x;
    for (int t = tid; t < 64 * 6; t += 256) ws[t] = w1[t];
    __syncthreads();

    const int p = blockIdx.x * 256 + tid;
    const int q = p / KNN;
    const int b = q >> 11;
    const int n = q & (NPTS - 1);
    const int j = idx[p];
    const float* xb = x + (size_t)b * 3 * NPTS;

    const float xi0 = xb[n], xi1 = xb[NPTS + n], xi2 = xb[2 * NPTS + n];
    const float f0 = xb[j] - xi0;
    const float f1 = xb[NPTS + j] - xi1;
    const float f2 = xb[2 * NPTS + j] - xi2;
    const float f3 = xi0, f4 = xi1, f5 = xi2;

    #pragma unroll 8
    for (int o = 0; o < 64; o++) {
        const float* w = ws + o * 6;
        float acc = fmaf(w[5], f5, fmaf(w[4], f4, fmaf(w[3], f3,
                    fmaf(w[2], f2, fmaf(w[1], f1, w[0] * f0)))));
        y1[(size_t)o * P1 + p] = acc;
    }
}

// ---------------------------------------------------------------------------
// bf16x3 MMA GEMM: Y[O,P] = W[O,Cin] * act(X[Cin,P]).
// CTA: 128p x NTILE o, k-chunks of 32 (two k16 sub-blocks), double-buffered.
// 8 warps = 4(p) x 2(o); warp tile 32p x NTILE/2. W pre-packed bf16 planes.
// Requires P%128==0, O%NTILE==0, Cin%32==0.
// Sub-block layout: AHI 0 (128x48B), ALO 6144, BHI 12288 (NTILE x 48B), BLO.
// ---------------------------------------------------------------------------
template <int NTILE>
__global__ __launch_bounds__(256)
void gemm_mma(const __nv_bfloat16* __restrict__ whi, const __nv_bfloat16* __restrict__ wlo,
              const float* __restrict__ X, float* __restrict__ Y, int Cin, int P,
              const float* __restrict__ scale, const float* __restrict__ shift,
              double* __restrict__ sumO, double* __restrict__ sqO) {
    constexpr int NA  = NTILE / 16;             // n-atoms per warp
    constexpr int SUB = 12288 + 2 * NTILE * 48; // bytes per k16 sub-block
    constexpr int BHI = 12288;
    constexpr int BLO = 12288 + NTILE * 48;

    extern __shared__ __align__(16) char dsm[];
    __shared__ float ssc[512], ssh[512];
    __shared__ float s_sum[NTILE], s_sq[NTILE];

    const int tid = threadIdx.x, wid = tid >> 5, lane = tid & 31;
    const int p0 = blockIdx.x * 128;
    const int o0 = blockIdx.y * NTILE;
    const bool bn = (scale != nullptr);

    if (bn) for (int c = tid; c < Cin; c += 256) { ssc[c] = scale[c]; ssh[c] = shift[c]; }
    for (int c = tid; c < NTILE; c += 256) { s_sum[c] = 0.f; s_sq[c] = 0.f; }
    __syncthreads();

    const int m0 = (wid & 3) * 32;              // warp p-base
    const int n0 = (wid >> 2) * (NTILE / 2);    // warp o-base
    const int g = lane >> 2, tq = lane & 3;

    // A global-load mapping per k16 sub-block
    const int kp = tid >> 5, p4 = tid & 31;

    float acc[2][NA][4];
    #pragma unroll
    for (int i = 0; i < 2; i++)
        #pragma unroll
        for (int j = 0; j < NA; j++)
            #pragma unroll
            for (int r = 0; r < 4; r++) acc[i][j][r] = 0.f;

    const int KT = Cin >> 5;                    // k32 chunks
    float4 va0[2], va1[2];                      // A prefetch (per sub)
    uint4 bvh[2], bvl[2];                       // B prefetch (<=2 idx iters)

    auto load_chunk = [&](int ci) {
        const int c0 = ci * 32;
        #pragma unroll
        for (int sub = 0; sub < 2; sub++) {
            const int cs = c0 + sub * 16 + 2 * kp;
            const float* xp = X + (size_t)cs * P + p0 + 4 * p4;
            float4 v0 = *reinterpret_cast<const float4*>(xp);
            float4 v1 = *reinterpret_cast<const float4*>(xp + P);
            if (bn) {
                float s0 = ssc[cs], h0 = ssh[cs];
                float s1 = ssc[cs + 1], h1 = ssh[cs + 1];
                v0.x = fmaxf(fmaf(v0.x, s0, h0), 0.f);
                v0.y = fmaxf(fmaf(v0.y, s0, h0), 0.f);
                v0.z = fmaxf(fmaf(v0.z, s0, h0), 0.f);
                v0.w = fmaxf(fmaf(v0.w, s0, h0), 0.f);
                v1.x = fmaxf(fmaf(v1.x, s1, h1), 0.f);
                v1.y = fmaxf(fmaf(v1.y, s1, h1), 0.f);
                v1.z = fmaxf(fmaf(v1.z, s1, h1), 0.f);
                v1.w = fmaxf(fmaf(v1.w, s1, h1), 0.f);
            }
            va0[sub] = v0; va1[sub] = v1;
        }
        #pragma unroll
        for (int it = 0; it < (NTILE == 128 ? 2 : 1); it++) {
            const int idx = it * 256 + tid;     // < NTILE*4
            const int o = idx >> 2, q8 = idx & 3;
            if (NTILE == 64 && idx >= NTILE * 4) continue;
            const size_t goff = (size_t)(o0 + o) * Cin + c0 + q8 * 8;
            bvh[it] = *reinterpret_cast<const uint4*>(whi + goff);
            bvl[it] = *reinterpret_cast<const uint4*>(wlo + goff);
        }
    };

    auto store_chunk = [&](int buf) {
        char* bb = dsm + buf * 2 * SUB;
        #pragma unroll
        for (int sub = 0; sub < 2; sub++) {
            char* blk = bb + sub * SUB;
            const float a0v[4] = {va0[sub].x, va0[sub].y, va0[sub].z, va0[sub].w};
            const float a1v[4] = {va1[sub].x, va1[sub].y, va1[sub].z, va1[sub].w};
            #pragma unroll
            for (int j = 0; j < 4; j++) {
                uint32_t lo;
                uint32_t hi = pack_hi(a0v[j], a1v[j], lo);
                uint32_t off = (uint32_t)(4 * p4 + j) * 48 + kp * 4;
                *reinterpret_cast<uint32_t*>(blk + off) = hi;
                *reinterpret_cast<uint32_t*>(blk + 6144 + off) = lo;
            }
        }
        #pragma unroll
        for (int it = 0; it < (NTILE == 128 ? 2 : 1); it++) {
            const int idx = it * 256 + tid;
            const int o = idx >> 2, q8 = idx & 3;
            if (NTILE == 64 && idx >= NTILE * 4) continue;
            char* blk = bb + (q8 >> 1) * SUB;
            uint32_t off = (uint32_t)o * 48 + (q8 & 1) * 16;
            *reinterpret_cast<uint4*>(blk + BHI + off) = bvh[it];
            *reinterpret_cast<uint4*>(blk + BLO + off) = bvl[it];
        }
    };

    load_chunk(0);
    store_chunk(0);
    __syncthreads();

    for (int kt = 0; kt < KT; kt++) {
        const int buf = kt & 1;
        if (kt + 1 < KT) load_chunk(kt + 1);

        #pragma unroll
        for (int sub = 0; sub < 2; sub++) {
            const uint32_t base = smem_u32(dsm) + buf * 2 * SUB + sub * SUB;
            uint32_t ah[2][4], al[2][4];
            #pragma unroll
            for (int ma = 0; ma < 2; ma++) {
                uint32_t roff = (uint32_t)(m0 + ma * 16 + (lane & 15)) * 48
                              + ((lane >> 4) & 1) * 16;
                LDSM_X4(ah[ma][0], ah[ma][1], ah[ma][2], ah[ma][3], base + roff);
                LDSM_X4(al[ma][0], al[ma][1], al[ma][2], al[ma][3], base + 6144 + roff);
            }
            #pragma unroll
            for (int jp = 0; jp < NA / 2; jp++) {
                uint32_t roff = (uint32_t)(n0 + jp * 16 + (lane & 7)
                              + ((lane >> 4) & 1) * 8) * 48 + ((lane >> 3) & 1) * 16;
                uint32_t bh0, bh1, bh2, bh3, bl0, bl1, bl2, bl3;
                LDSM_X4(bh0, bh1, bh2, bh3, base + BHI + roff);
                LDSM_X4(bl0, bl1, bl2, bl3, base + BLO + roff);
                #pragma unroll
                for (int ma = 0; ma < 2; ma++) {
                    MMA_BF16(acc[ma][2 * jp], ah[ma], bh0, bh1);
                    MMA_BF16(acc[ma][2 * jp], ah[ma], bl0, bl1);
                    MMA_BF16(acc[ma][2 * jp], al[ma], bh0, bh1);
                    MMA_BF16(acc[ma][2 * jp + 1], ah[ma], bh2, bh3);
                    MMA_BF16(acc[ma][2 * jp + 1], ah[ma], bl2, bl3);
                    MMA_BF16(acc[ma][2 * jp + 1], al[ma], bh2, bh3);
                }
            }
        }
        __syncthreads();

        if (kt + 1 < KT) {
            store_chunk(buf ^ 1);
            __syncthreads();
        }
    }

    // ---- epilogue: stage D via smem, coalesced store + fused stats ----
    float (*yt)[132] = reinterpret_cast<float(*)[132]>(dsm);
    #pragma unroll
    for (int ma = 0; ma < 2; ma++) {
        const int p = m0 + ma * 16 + g;
        #pragma unroll
        for (int na = 0; na < NA; na++) {
            const int o = n0 + na * 8 + tq * 2;
            yt[o][p]         = acc[ma][na][0];
            yt[o + 1][p]     = acc[ma][na][1];
            yt[o][p + 8]     = acc[ma][na][2];
            yt[o + 1][p + 8] = acc[ma][na][3];
        }
    }
    __syncthreads();

    {   // stats: 256/NTILE threads per o-row
        constexpr int TPO = 256 / NTILE;
        constexpr int SEG = 128 / TPO;
        const int o = tid / TPO, seg = (tid % TPO) * SEG;
        float s = 0.f, q2 = 0.f;
        #pragma unroll
        for (int i = 0; i < SEG; i++) {
            float v = yt[o][seg + i];
            s += v;
            q2 = fmaf(v, v, q2);
        }
        atomicAdd(&s_sum[o], s);
        atomicAdd(&s_sq[o], q2);
    }

    #pragma unroll
    for (int i = 0; i < NTILE / 8; i++) {
        const int lin = i * 256 + tid;
        const int o = lin >> 5, pp = (lin & 31) * 4;
        *reinterpret_cast<float4*>(&Y[(size_t)(o0 + o) * P + p0 + pp]) =
            *reinterpret_cast<const float4*>(&yt[o][pp]);
    }
    __syncthreads();
    if (tid < NTILE) {
        atomicAdd(&sumO[o0 + tid], (double)s_sum[tid]);
        atomicAdd(&sqO[o0 + tid], (double)s_sq[tid]);
    }
}

// ---------------------------------------------------------------------------
// Per-channel sum / sumsq (double) over raw y (layer 1 only).
// ---------------------------------------------------------------------------
__global__ void stats_kernel(const float* __restrict__ Yv, double* __restrict__ sum,
                             double* __restrict__ sumsq, int P) {
    const int c = blockIdx.y;
    const float* row = Yv + (size_t)c * P;
    const int base = blockIdx.x * 4096 + threadIdx.x;
    double s = 0.0, ss = 0.0;
    #pragma unroll
    for (int u = 0; u < 16; u++) {
        int p = base + u * 256;
        if (p < P) { double v = (double)row[p]; s += v; ss += v * v; }
    }
    #pragma unroll
    for (int off = 16; off; off >>= 1) {
        s  += __shfl_down_sync(0xffffffffu, s,  off);
        ss += __shfl_down_sync(0xffffffffu, ss, off);
    }
    __shared__ double sw[8], ssw[8];
    const int lane = threadIdx.x & 31, w = threadIdx.x >> 5;
    if (lane == 0) { sw[w] = s; ssw[w] = ss; }
    __syncthreads();
    if (threadIdx.x == 0) {
        double S = 0.0, SS = 0.0;
        #pragma unroll
        for (int i = 0; i < 8; i++) { S += sw[i]; SS += ssw[i]; }
        atomicAdd(&sum[c], S);
        atomicAdd(&sumsq[c], SS);
    }
}

__global__ void finalize_kernel(const float* __restrict__ g, const float* __restrict__ bb,
                                const double* __restrict__ sum, const double* __restrict__ sumsq,
                                float* __restrict__ scale, float* __restrict__ shift,
                                int C, double invcnt) {
    int c = threadIdx.x;
    if (c >= C) return;
    double m = sum[c] * invcnt;
    double v = sumsq[c] * invcnt - m * m;
    if (v < 0.0) v = 0.0;
    float rstd = rsqrtf((float)v + 1e-5f);
    float sc = g[c] * rstd;
    scale[c] = sc;
    shift[c] = bb[c] - (float)m * sc;
}

// ---------------------------------------------------------------------------
// BN + ReLU + max over k=20; writes into concat buffer at channel offset.
// ---------------------------------------------------------------------------
__global__ void max_kernel(const float* __restrict__ Yv, const float* __restrict__ scale,
                           const float* __restrict__ shift, float* __restrict__ outp, int C) {
    const int t = blockIdx.x * 256 + threadIdx.x;
    const int c = t >> 14;
    const int q = t & 16383;
    const float* src = Yv + (size_t)c * P1 + (size_t)q * KNN;
    const float sc = scale[c], sh = shift[c];
    float m = 0.f;
    #pragma unroll
    for (int k = 0; k < KNN; k++) m = fmaxf(m, fmaf(src[k], sc, sh));
    outp[(size_t)c * Q + q] = m;
}

__global__ void final_kernel(const float* __restrict__ y5, const float* __restrict__ scale,
                             const float* __restrict__ shift, float* __restrict__ out) {
    const int t = blockIdx.x * 256 + threadIdx.x;
    const int n = t & (NPTS - 1);
    const int c = (t >> 11) & 511;
    const int b = t >> 20;
    float v = y5[(size_t)c * Q + b * NPTS + n];
    out[t] = fmaxf(fmaf(v, scale[c], shift[c]), 0.f);
}

// ---------------------------------------------------------------------------
extern "C" void kernel_launch(void* const* d_in, const int* in_sizes, int n_in,
                              void* d_out, int out_size) {
    const float* x  = (const float*)d_in[0];
    const float* w1 = (const float*)d_in[1];
    const float* g1 = (const float*)d_in[2];
    const float* b1 = (const float*)d_in[3];
    const float* w2 = (const float*)d_in[4];
    const float* g2 = (const float*)d_in[5];
    const float* b2 = (const float*)d_in[6];
    const float* w3 = (const float*)d_in[7];
    const float* g3 = (const float*)d_in[8];
    const float* b3 = (const float*)d_in[9];
    const float* w4 = (const float*)d_in[10];
    const float* g4 = (const float*)d_in[11];
    const float* b4 = (const float*)d_in[12];
    const float* w5 = (const float*)d_in[13];
    const float* g5 = (const float*)d_in[14];
    const float* b5 = (const float*)d_in[15];
    float* out = (float*)d_out;

    int *idxp; float *y1, *y2, *y3, *y4, *xcat, *y5, *scal, *shif;
    double *sum, *sumsq;
    __nv_bfloat16 *whi, *wlo;
    cudaGetSymbolAddress((void**)&idxp,  g_idx);
    cudaGetSymbolAddress((void**)&y1,    g_y1);
    cudaGetSymbolAddress((void**)&y2,    g_y2);
    cudaGetSymbolAddress((void**)&y3,    g_y3);
    cudaGetSymbolAddress((void**)&y4,    g_y4);
    cudaGetSymbolAddress((void**)&xcat,  g_xcat);
    cudaGetSymbolAddress((void**)&y5,    g_y5);
    cudaGetSymbolAddress((void**)&sum,   g_sum);
    cudaGetSymbolAddress((void**)&sumsq, g_sumsq);
    cudaGetSymbolAddress((void**)&scal,  g_scale);
    cudaGetSymbolAddress((void**)&shif,  g_shift);
    cudaGetSymbolAddress((void**)&whi,   g_whi);
    cudaGetSymbolAddress((void**)&wlo,   g_wlo);

    // dynamic smem: 4 sub-blocks (2 buffers x 2 k16)
    const int smem64  = 4 * (12288 + 2 * 64  * 48);   // 73728
    const int smem128 = 4 * (12288 + 2 * 128 * 48);   // 98304
    cudaFuncSetAttribute(gemm_mma<64>,  cudaFuncAttributeMaxDynamicSharedMemorySize, smem64);
    cudaFuncSetAttribute(gemm_mma<128>, cudaFuncAttributeMaxDynamicSharedMemorySize, smem128);

    const double ic1 = 1.0 / (double)P1;
    const double ic5 = 1.0 / (double)Q;

    cudaMemsetAsync(sum,   0, 1024 * sizeof(double));
    cudaMemsetAsync(sumsq, 0, 1024 * sizeof(double));

    // pack weights to bf16 hi/lo planes (offsets: w2@0, w3@4096, w4@12288, w5@45056)
    pack_w<<<16, 256>>>(w2, whi + 0,     wlo + 0,     4096);
    pack_w<<<32, 256>>>(w3, whi + 4096,  wlo + 4096,  8192);
    pack_w<<<128, 256>>>(w4, whi + 12288, wlo + 12288, 32768);
    pack_w<<<1024, 256>>>(w5, whi + 45056, wlo + 45056, 262144);

    knn_kernel<<<Q / 4, 128>>>(x, idxp);
    layer1_kernel<<<P1 / 256, 256>>>(x, idxp, w1, y1);

    stats_kernel<<<dim3(80, 64), 256>>>(y1, sum + 0, sumsq + 0, P1);
    finalize_kernel<<<1, 64>>>(g1, b1, sum + 0, sumsq + 0, scal + 0, shif + 0, 64, ic1);
    max_kernel<<<64 * Q / 256, 256>>>(y1, scal + 0, shif + 0, xcat, 64);

    gemm_mma<64><<<dim3(P1 / 128, 1), 256, smem64>>>(
        whi + 0, wlo + 0, y1, y2, 64, P1, scal + 0, shif + 0, sum + 64, sumsq + 64);
    finalize_kernel<<<1, 64>>>(g2, b2, sum + 64, sumsq + 64, scal + 64, shif + 64, 64, ic1);
    max_kernel<<<64 * Q / 256, 256>>>(y2, scal + 64, shif + 64, xcat + (size_t)64 * Q, 64);

    gemm_mma<128><<<dim3(P1 / 128, 1), 256, smem128>>>(
        whi + 4096, wlo + 4096, y2, y3, 64, P1, scal + 64, shif + 64, sum + 128, sumsq + 128);
    finalize_kernel<<<1, 128>>>(g3, b3, sum + 128, sumsq + 128, scal + 128, shif + 128, 128, ic1);
    max_kernel<<<128 * Q / 256, 256>>>(y3, scal + 128, shif + 128, xcat + (size_t)128 * Q, 128);

    gemm_mma<128><<<dim3(P1 / 128, 2), 256, smem128>>>(
        whi + 12288, wlo + 12288, y3, y4, 128, P1, scal + 128, shif + 128, sum + 256, sumsq + 256);
    finalize_kernel<<<1, 256>>>(g4, b4, sum + 256, sumsq + 256, scal + 256, shif + 256, 256, ic1);
    max_kernel<<<256 * Q / 256, 256>>>(y4, scal + 256, shif + 256, xcat + (size_t)256 * Q, 256);

    gemm_mma<128><<<dim3(Q / 128, 4), 256, smem128>>>(
        whi + 45056, wlo + 45056, xcat, y5, 512, Q, nullptr, nullptr, sum + 512, sumsq + 512);
    finalize_kernel<<<1, 512>>>(g5, b5, sum + 512, sumsq + 512, scal + 512, shif + 512, 512, ic5);
    final_kernel<<<(BATCH * 512 * NPTS) / 256, 256>>>(y5, scal + 512, shif + 512, out);
}